// round 7
// baseline (speedup 1.0000x reference)
#include <cuda_runtime.h>
#include <cuda_bf16.h>

#define NN 100000
#define EE 3200000
#define K_SLOT 80
#define SPILL_MAX 65536

#define E_BLOCKS 592
#define E_WARPS (E_BLOCKS * 8)

// ---------------- scratch (device globals; no allocations) ----------------
__device__ int   g_esrc2[NN * K_SLOT];   // bucketed src per dst (fixed stride)
__device__ int   g_cnt[NN];
__device__ int   g_spill_s[SPILL_MAX];
__device__ int   g_spill_d[SPILL_MAX];
__device__ int   g_spill_cnt;
__device__ float g_xl1[NN * 16];
__device__ float g_xr1[NN * 16];
__device__ float g_xl2[NN * 8];
__device__ float g_xr2[NN * 8];
__device__ int   g_is64;

// ---------------- helpers ----------------
__device__ __forceinline__ float lrelu02(float x) {
    return fmaxf(x, 0.2f * x);
}

__device__ __forceinline__ void fma2(float2& d, float2 a, float2 b, float2 c) {
    asm("fma.rn.f32x2 %0, %1, %2, %3;"
        : "=l"(reinterpret_cast<unsigned long long&>(d))
        : "l"(reinterpret_cast<unsigned long long&>(a)),
          "l"(reinterpret_cast<unsigned long long&>(b)),
          "l"(reinterpret_cast<unsigned long long&>(c)));
}

// ---------------- K1: zero counters + detect dtype ----------------
__global__ void init_kernel(const long long* __restrict__ ei) {
    int i = blockIdx.x * blockDim.x + threadIdx.x;
    if (i < NN) g_cnt[i] = 0;
    if (blockIdx.x == 0) {
        if (threadIdx.x == 0) g_spill_cnt = 0;
        int bad = 0;
        for (int j = threadIdx.x; j < 2048; j += 1024) {
            long long v = ei[j];
            if (v < 0 || v >= (long long)NN) bad = 1;
        }
        bad = __syncthreads_or(bad);
        if (threadIdx.x == 0) g_is64 = bad ? 0 : 1;
    }
}

// ---------------- K2: single-pass bucket build ----------------
__global__ void build_kernel(const void* __restrict__ ei) {
    int i = blockIdx.x * blockDim.x + threadIdx.x;
    if (i >= EE) return;
    int s, d;
    if (g_is64) {
        const long long* p = (const long long*)ei;
        s = (int)p[i];
        d = (int)p[EE + i];
    } else {
        const int* p = (const int*)ei;
        s = p[i];
        d = p[EE + i];
    }
    int p = atomicAdd(&g_cnt[d], 1);
    if (p < K_SLOT) {
        g_esrc2[d * K_SLOT + p] = s;
    } else {
        int q = atomicAdd(&g_spill_cnt, 1);
        if (q < SPILL_MAX) { g_spill_s[q] = s; g_spill_d[q] = d; }
    }
}

// ---------------- K3: GEMM1 — f32x2 packed FMA ----------------
#define G_NODES 512
#define G_KC    16
#define G_XS    (G_KC + 1)
#define G_SMEM  ((256 * 32 + G_NODES * G_XS) * sizeof(float))

__global__ void __launch_bounds__(256, 2)
gemm1_kernel(const float* __restrict__ x,
             const float* __restrict__ W1l,
             const float* __restrict__ W1r) {
    extern __shared__ float smem[];
    float* Ws = smem;                 // [256 k][32 c]
    float* xs = smem + 256 * 32;      // [512 node][G_XS]

    int t = threadIdx.x;
    for (int i = t; i < 256 * 16; i += 256) {
        int k = i >> 4, c = i & 15;
        Ws[k * 32 + c]      = W1l[i];
        Ws[k * 32 + 16 + c] = W1r[i];
    }

    int nodeBase = blockIdx.x * G_NODES;
    int half = t & 1;
    int ng = (t >> 1) * 4;

    float2 acc[4][8];
#pragma unroll
    for (int m = 0; m < 4; m++)
#pragma unroll
        for (int j = 0; j < 8; j++) acc[m][j] = make_float2(0.f, 0.f);

    for (int kc = 0; kc < 256; kc += G_KC) {
        __syncthreads();
#pragma unroll
        for (int it = 0; it < 8; it++) {
            int idx = t + 256 * it;
            int node = idx >> 2;
            int k4 = (idx & 3) * 4;
            int gnode = nodeBase + node;
            float4 v = (gnode < NN)
                ? *(const float4*)(x + (size_t)gnode * 256 + kc + k4)
                : make_float4(0.f, 0.f, 0.f, 0.f);
            float* p = xs + node * G_XS + k4;
            p[0] = v.x; p[1] = v.y; p[2] = v.z; p[3] = v.w;
        }
        __syncthreads();

#pragma unroll
        for (int k = 0; k < G_KC; k++) {
            const float4* wp = (const float4*)&Ws[(kc + k) * 32 + half * 16];
            float4 w0 = wp[0], w1 = wp[1], w2 = wp[2], w3 = wp[3];
            float2 w[8];
            w[0] = make_float2(w0.x, w0.y); w[1] = make_float2(w0.z, w0.w);
            w[2] = make_float2(w1.x, w1.y); w[3] = make_float2(w1.z, w1.w);
            w[4] = make_float2(w2.x, w2.y); w[5] = make_float2(w2.z, w2.w);
            w[6] = make_float2(w3.x, w3.y); w[7] = make_float2(w3.z, w3.w);
#pragma unroll
            for (int m = 0; m < 4; m++) {
                float xm = xs[(ng + m) * G_XS + k];
                float2 xp = make_float2(xm, xm);
#pragma unroll
                for (int j = 0; j < 8; j++)
                    fma2(acc[m][j], xp, w[j], acc[m][j]);
            }
        }
    }

    float* base = half ? g_xr1 : g_xl1;
#pragma unroll
    for (int m = 0; m < 4; m++) {
        int node = nodeBase + ng + m;
        if (node < NN) {
            float* dstp = base + node * 16;
            *(float4*)(dstp + 0)  = make_float4(acc[m][0].x, acc[m][0].y, acc[m][1].x, acc[m][1].y);
            *(float4*)(dstp + 4)  = make_float4(acc[m][2].x, acc[m][2].y, acc[m][3].x, acc[m][3].y);
            *(float4*)(dstp + 8)  = make_float4(acc[m][4].x, acc[m][4].y, acc[m][5].x, acc[m][5].y);
            *(float4*)(dstp + 12) = make_float4(acc[m][6].x, acc[m][6].y, acc[m][7].x, acc[m][7].y);
        }
    }
}

// ---------------- edge slot processing (layer 1) ----------------
__device__ __forceinline__ void e1_slot(const int* ep, int j, int len,
                                        float4 aa, float4 xr, int h,
                                        float4& acc, float& den) {
    bool valid = j < len;
    int s = valid ? ep[j] : 0;
    float4 xl = *((const float4*)(g_xl1 + s * 16) + h);
    float lg = aa.x * lrelu02(xl.x + xr.x)
             + aa.y * lrelu02(xl.y + xr.y)
             + aa.z * lrelu02(xl.z + xr.z)
             + aa.w * lrelu02(xl.w + xr.w);
    float ex = valid ? __expf(lg) : 0.0f;
    den += ex;
    acc.x = fmaf(ex, xl.x, acc.x);
    acc.y = fmaf(ex, xl.y, acc.y);
    acc.z = fmaf(ex, xl.z, acc.z);
    acc.w = fmaf(ex, xl.w, acc.w);
}

// ---------------- K4: edge layer 1 + fused node2 — persistent warps --------
// 4 lanes per edge (lane = head = float4), 8 edge slots, unroll 4 deep:
// all 32 gathers of a typical node are in flight before any exp is consumed.
__global__ void __launch_bounds__(256)
edge1_kernel(const float* __restrict__ a1,
             const float* __restrict__ b1,
             const float* __restrict__ W2l,
             const float* __restrict__ W2r) {
    int gwarp = (blockIdx.x * blockDim.x + threadIdx.x) >> 5;
    int lane = threadIdx.x & 31;
    int h = lane & 3;
    int eg = lane >> 2;

    // preload constants once per warp
    float w2[16];
#pragma unroll
    for (int k = 0; k < 16; k++) {
        if (lane < 8)       w2[k] = __ldg(W2l + k * 8 + lane);
        else if (lane < 16) w2[k] = __ldg(W2r + k * 8 + (lane - 8));
        else                w2[k] = 0.0f;
    }
    float4 aa = __ldg((const float4*)a1 + h);
    float4 bb = __ldg((const float4*)b1 + h);

    for (int d = gwarp; d < NN; d += E_WARPS) {
        int cnt = g_cnt[d];
        int len = cnt < K_SLOT ? cnt : K_SLOT;
        const int* ep = g_esrc2 + d * K_SLOT;
        float4 xr = *((const float4*)(g_xr1 + d * 16) + h);

        float4 acc0 = make_float4(0.f, 0.f, 0.f, 0.f), acc1 = acc0, acc2 = acc0, acc3 = acc0;
        float den0 = 0.f, den1 = 0.f, den2 = 0.f, den3 = 0.f;
        int lenUp = (len + 7) & ~7;
        int j = eg;
        for (; j + 24 < lenUp; j += 32) {
            e1_slot(ep, j,      len, aa, xr, h, acc0, den0);
            e1_slot(ep, j + 8,  len, aa, xr, h, acc1, den1);
            e1_slot(ep, j + 16, len, aa, xr, h, acc2, den2);
            e1_slot(ep, j + 24, len, aa, xr, h, acc3, den3);
        }
        for (; j < lenUp; j += 8)
            e1_slot(ep, j, len, aa, xr, h, acc0, den0);

        // spill fallback (empty in practice)
        if (cnt > K_SLOT) {
            int ns = g_spill_cnt; if (ns > SPILL_MAX) ns = SPILL_MAX;
            for (int q = 0; q < ns; q++) {
                if (g_spill_d[q] == d && eg == 0) {
                    int s = g_spill_s[q];
                    float4 xl = *((const float4*)(g_xl1 + s * 16) + h);
                    float lg = aa.x * lrelu02(xl.x + xr.x)
                             + aa.y * lrelu02(xl.y + xr.y)
                             + aa.z * lrelu02(xl.z + xr.z)
                             + aa.w * lrelu02(xl.w + xr.w);
                    float ex = __expf(lg);
                    den0 += ex;
                    acc0.x = fmaf(ex, xl.x, acc0.x);
                    acc0.y = fmaf(ex, xl.y, acc0.y);
                    acc0.z = fmaf(ex, xl.z, acc0.z);
                    acc0.w = fmaf(ex, xl.w, acc0.w);
                }
            }
        }
        float4 acc;
        acc.x = (acc0.x + acc1.x) + (acc2.x + acc3.x);
        acc.y = (acc0.y + acc1.y) + (acc2.y + acc3.y);
        acc.z = (acc0.z + acc1.z) + (acc2.z + acc3.z);
        acc.w = (acc0.w + acc1.w) + (acc2.w + acc3.w);
        float den = (den0 + den1) + (den2 + den3);
#pragma unroll
        for (int o = 4; o < 32; o <<= 1) {
            acc.x += __shfl_xor_sync(0xFFFFFFFFu, acc.x, o);
            acc.y += __shfl_xor_sync(0xFFFFFFFFu, acc.y, o);
            acc.z += __shfl_xor_sync(0xFFFFFFFFu, acc.z, o);
            acc.w += __shfl_xor_sync(0xFFFFFFFFu, acc.w, o);
            den   += __shfl_xor_sync(0xFFFFFFFFu, den, o);
        }

        // fused node2: normalize + bias + ELU, 16->8|8 transform via shfl
        float inv = 1.0f / (den + 1e-16f);
        float v4[4];
        {
            float t0 = acc.x * inv + bb.x;
            float t1 = acc.y * inv + bb.y;
            float t2 = acc.z * inv + bb.z;
            float t3 = acc.w * inv + bb.w;
            v4[0] = (t0 > 0.0f) ? t0 : (__expf(t0) - 1.0f);
            v4[1] = (t1 > 0.0f) ? t1 : (__expf(t1) - 1.0f);
            v4[2] = (t2 > 0.0f) ? t2 : (__expf(t2) - 1.0f);
            v4[3] = (t3 > 0.0f) ? t3 : (__expf(t3) - 1.0f);
        }
        float o = 0.0f;
#pragma unroll
        for (int k = 0; k < 16; k++) {
            float vk = __shfl_sync(0xFFFFFFFFu, v4[k & 3], k >> 2);
            o = fmaf(vk, w2[k], o);
        }
        if (lane < 8)       g_xl2[d * 8 + lane] = o;
        else if (lane < 16) g_xr2[d * 8 + (lane - 8)] = o;
    }
}

// ---------------- edge slot processing (layer 2) ----------------
__device__ __forceinline__ void e2_slot(const int* ep, int j, int len,
                                        float4 aa, float4 xr, int hf,
                                        float4& acc, float& den) {
    bool valid = j < len;
    int s = valid ? ep[j] : 0;
    float4 xl = *((const float4*)(g_xl2 + s * 8) + hf);
    float t = aa.x * lrelu02(xl.x + xr.x)
            + aa.y * lrelu02(xl.y + xr.y)
            + aa.z * lrelu02(xl.z + xr.z)
            + aa.w * lrelu02(xl.w + xr.w);
    t += __shfl_xor_sync(0xFFFFFFFFu, t, 1);
    float ex = valid ? __expf(t) : 0.0f;
    den += ex;
    acc.x = fmaf(ex, xl.x, acc.x);
    acc.y = fmaf(ex, xl.y, acc.y);
    acc.z = fmaf(ex, xl.z, acc.z);
    acc.w = fmaf(ex, xl.w, acc.w);
}

// ---------------- K5: edge layer 2 — persistent warps, fused output --------
__global__ void __launch_bounds__(256)
edge2_kernel(const float* __restrict__ a2,
             const float* __restrict__ b2,
             float* __restrict__ out) {
    int gwarp = (blockIdx.x * blockDim.x + threadIdx.x) >> 5;
    int lane = threadIdx.x & 31;
    int hf = lane & 1;
    int eg = lane >> 1;

    float4 aa = __ldg((const float4*)a2 + hf);
    float4 bb = __ldg((const float4*)b2 + (lane & 1));

    for (int d = gwarp; d < NN; d += E_WARPS) {
        int cnt = g_cnt[d];
        int len = cnt < K_SLOT ? cnt : K_SLOT;
        const int* ep = g_esrc2 + d * K_SLOT;
        float4 xr = *((const float4*)(g_xr2 + d * 8) + hf);

        float4 acc0 = make_float4(0.f, 0.f, 0.f, 0.f), acc1 = acc0;
        float den0 = 0.f, den1 = 0.f;
        int lenUp = (len + 15) & ~15;
        int j = eg;
        for (; j + 16 < lenUp; j += 32) {
            e2_slot(ep, j,      len, aa, xr, hf, acc0, den0);
            e2_slot(ep, j + 16, len, aa, xr, hf, acc1, den1);
        }
        for (; j < lenUp; j += 16)
            e2_slot(ep, j, len, aa, xr, hf, acc0, den0);

        if (cnt > K_SLOT) {
            int ns = g_spill_cnt; if (ns > SPILL_MAX) ns = SPILL_MAX;
            for (int q = 0; q < ns; q++) {
                if (g_spill_d[q] == d && eg == 0) {
                    int s = g_spill_s[q];
                    float4 xl = *((const float4*)(g_xl2 + s * 8) + hf);
                    float t = aa.x * lrelu02(xl.x + xr.x)
                            + aa.y * lrelu02(xl.y + xr.y)
                            + aa.z * lrelu02(xl.z + xr.z)
                            + aa.w * lrelu02(xl.w + xr.w);
                    t += __shfl_xor_sync(0x3u, t, 1);
                    float ex = __expf(t);
                    den0 += ex;
                    acc0.x = fmaf(ex, xl.x, acc0.x);
                    acc0.y = fmaf(ex, xl.y, acc0.y);
                    acc0.z = fmaf(ex, xl.z, acc0.z);
                    acc0.w = fmaf(ex, xl.w, acc0.w);
                }
            }
        }
        float4 acc;
        acc.x = acc0.x + acc1.x;
        acc.y = acc0.y + acc1.y;
        acc.z = acc0.z + acc1.z;
        acc.w = acc0.w + acc1.w;
        float den = den0 + den1;
#pragma unroll
        for (int o = 2; o < 32; o <<= 1) {
            acc.x += __shfl_xor_sync(0xFFFFFFFFu, acc.x, o);
            acc.y += __shfl_xor_sync(0xFFFFFFFFu, acc.y, o);
            acc.z += __shfl_xor_sync(0xFFFFFFFFu, acc.z, o);
            acc.w += __shfl_xor_sync(0xFFFFFFFFu, acc.w, o);
            den   += __shfl_xor_sync(0xFFFFFFFFu, den, o);
        }

        if (lane < 2) {
            float inv = 1.0f / (den + 1e-16f);
            float4 r;
            r.x = 1.0f / (1.0f + __expf(-(acc.x * inv + bb.x)));
            r.y = 1.0f / (1.0f + __expf(-(acc.y * inv + bb.y)));
            r.z = 1.0f / (1.0f + __expf(-(acc.z * inv + bb.z)));
            r.w = 1.0f / (1.0f + __expf(-(acc.w * inv + bb.w)));
            *((float4*)(out + d * 8) + lane) = r;
        }
    }
}

// ---------------- launch ----------------
extern "C" void kernel_launch(void* const* d_in, const int* in_sizes, int n_in,
                              void* d_out, int out_size) {
    const float* x   = (const float*)d_in[0];
    const void*  ei  = d_in[1];
    const float* W1l = (const float*)d_in[2];
    const float* W1r = (const float*)d_in[3];
    const float* a1  = (const float*)d_in[4];
    const float* b1  = (const float*)d_in[5];
    const float* W2l = (const float*)d_in[6];
    const float* W2r = (const float*)d_in[7];
    const float* a2  = (const float*)d_in[8];
    const float* b2  = (const float*)d_in[9];
    float* out = (float*)d_out;

    static bool configured = false;
    static cudaStream_t s2;
    static cudaEvent_t evA, evB;
    if (!configured) {
        cudaFuncSetAttribute(gemm1_kernel,
                             cudaFuncAttributeMaxDynamicSharedMemorySize,
                             (int)G_SMEM);
        cudaStreamCreateWithFlags(&s2, cudaStreamNonBlocking);
        cudaEventCreateWithFlags(&evA, cudaEventDisableTiming);
        cudaEventCreateWithFlags(&evB, cudaEventDisableTiming);
        configured = true;
    }

    const int EB = (EE + 255) / 256;

    // fork: gemm1 on s2 in parallel with CSR build on default stream
    cudaEventRecord(evA, 0);
    cudaStreamWaitEvent(s2, evA, 0);
    gemm1_kernel<<<(NN + G_NODES - 1) / G_NODES, 256, G_SMEM, s2>>>(x, W1l, W1r);
    cudaEventRecord(evB, s2);

    init_kernel<<<(NN + 1023) / 1024, 1024>>>((const long long*)ei);
    build_kernel<<<EB, 256>>>(ei);

    // join
    cudaStreamWaitEvent(0, evB, 0);
    edge1_kernel<<<E_BLOCKS, 256>>>(a1, b1, W2l, W2r);
    edge2_kernel<<<E_BLOCKS, 256>>>(a2, b2, out);
}

// round 8
// speedup vs baseline: 1.4201x; 1.4201x over previous
#include <cuda_runtime.h>
#include <cuda_bf16.h>

#define NN 100000
#define EE 3200000
#define K_SLOT 80
#define SPILL_MAX 65536

// ---------------- scratch (device globals; no allocations) ----------------
__device__ int   g_esrc2[NN * K_SLOT];   // bucketed src per dst (fixed stride)
__device__ int   g_cnt[NN];
__device__ int   g_spill_s[SPILL_MAX];
__device__ int   g_spill_d[SPILL_MAX];
__device__ int   g_spill_cnt;
__device__ float g_xl1[NN * 16];
__device__ float g_xr1[NN * 16];
__device__ float g_xl2[NN * 8];
__device__ float g_xr2[NN * 8];
__device__ int   g_is64;

// ---------------- helpers ----------------
__device__ __forceinline__ float lrelu02(float x) {
    return fmaxf(x, 0.2f * x);
}

__device__ __forceinline__ void fma2(float2& d, float2 a, float2 b, float2 c) {
    asm("fma.rn.f32x2 %0, %1, %2, %3;"
        : "=l"(reinterpret_cast<unsigned long long&>(d))
        : "l"(reinterpret_cast<unsigned long long&>(a)),
          "l"(reinterpret_cast<unsigned long long&>(b)),
          "l"(reinterpret_cast<unsigned long long&>(c)));
}

// ---------------- K1: zero counters + detect dtype ----------------
__global__ void init_kernel(const long long* __restrict__ ei) {
    int i = blockIdx.x * blockDim.x + threadIdx.x;
    if (i < NN) g_cnt[i] = 0;
    if (blockIdx.x == 0) {
        if (threadIdx.x == 0) g_spill_cnt = 0;
        int bad = 0;
        for (int j = threadIdx.x; j < 2048; j += 1024) {
            long long v = ei[j];
            if (v < 0 || v >= (long long)NN) bad = 1;
        }
        bad = __syncthreads_or(bad);
        if (threadIdx.x == 0) g_is64 = bad ? 0 : 1;
    }
}

// ---------------- K2: single-pass bucket build ----------------
__global__ void build_kernel(const void* __restrict__ ei) {
    int i = blockIdx.x * blockDim.x + threadIdx.x;
    if (i >= EE) return;
    int s, d;
    if (g_is64) {
        const long long* p = (const long long*)ei;
        s = (int)p[i];
        d = (int)p[EE + i];
    } else {
        const int* p = (const int*)ei;
        s = p[i];
        d = p[EE + i];
    }
    int p = atomicAdd(&g_cnt[d], 1);
    if (p < K_SLOT) {
        g_esrc2[d * K_SLOT + p] = s;
    } else {
        int q = atomicAdd(&g_spill_cnt, 1);
        if (q < SPILL_MAX) { g_spill_s[q] = s; g_spill_d[q] = d; }
    }
}

// ---------------- K3: GEMM1 — f32x2 packed FMA ----------------
#define G_NODES 512
#define G_KC    16
#define G_XS    (G_KC + 1)
#define G_SMEM  ((256 * 32 + G_NODES * G_XS) * sizeof(float))

__global__ void __launch_bounds__(256, 2)
gemm1_kernel(const float* __restrict__ x,
             const float* __restrict__ W1l,
             const float* __restrict__ W1r) {
    extern __shared__ float smem[];
    float* Ws = smem;                 // [256 k][32 c]
    float* xs = smem + 256 * 32;      // [512 node][G_XS]

    int t = threadIdx.x;
    for (int i = t; i < 256 * 16; i += 256) {
        int k = i >> 4, c = i & 15;
        Ws[k * 32 + c]      = W1l[i];
        Ws[k * 32 + 16 + c] = W1r[i];
    }

    int nodeBase = blockIdx.x * G_NODES;
    int half = t & 1;
    int ng = (t >> 1) * 4;

    float2 acc[4][8];
#pragma unroll
    for (int m = 0; m < 4; m++)
#pragma unroll
        for (int j = 0; j < 8; j++) acc[m][j] = make_float2(0.f, 0.f);

    for (int kc = 0; kc < 256; kc += G_KC) {
        __syncthreads();
#pragma unroll
        for (int it = 0; it < 8; it++) {
            int idx = t + 256 * it;
            int node = idx >> 2;
            int k4 = (idx & 3) * 4;
            int gnode = nodeBase + node;
            float4 v = (gnode < NN)
                ? *(const float4*)(x + (size_t)gnode * 256 + kc + k4)
                : make_float4(0.f, 0.f, 0.f, 0.f);
            float* p = xs + node * G_XS + k4;
            p[0] = v.x; p[1] = v.y; p[2] = v.z; p[3] = v.w;
        }
        __syncthreads();

#pragma unroll
        for (int k = 0; k < G_KC; k++) {
            const float4* wp = (const float4*)&Ws[(kc + k) * 32 + half * 16];
            float4 w0 = wp[0], w1 = wp[1], w2 = wp[2], w3 = wp[3];
            float2 w[8];
            w[0] = make_float2(w0.x, w0.y); w[1] = make_float2(w0.z, w0.w);
            w[2] = make_float2(w1.x, w1.y); w[3] = make_float2(w1.z, w1.w);
            w[4] = make_float2(w2.x, w2.y); w[5] = make_float2(w2.z, w2.w);
            w[6] = make_float2(w3.x, w3.y); w[7] = make_float2(w3.z, w3.w);
#pragma unroll
            for (int m = 0; m < 4; m++) {
                float xm = xs[(ng + m) * G_XS + k];
                float2 xp = make_float2(xm, xm);
#pragma unroll
                for (int j = 0; j < 8; j++)
                    fma2(acc[m][j], xp, w[j], acc[m][j]);
            }
        }
    }

    float* base = half ? g_xr1 : g_xl1;
#pragma unroll
    for (int m = 0; m < 4; m++) {
        int node = nodeBase + ng + m;
        if (node < NN) {
            float* dstp = base + node * 16;
            *(float4*)(dstp + 0)  = make_float4(acc[m][0].x, acc[m][0].y, acc[m][1].x, acc[m][1].y);
            *(float4*)(dstp + 4)  = make_float4(acc[m][2].x, acc[m][2].y, acc[m][3].x, acc[m][3].y);
            *(float4*)(dstp + 8)  = make_float4(acc[m][4].x, acc[m][4].y, acc[m][5].x, acc[m][5].y);
            *(float4*)(dstp + 12) = make_float4(acc[m][6].x, acc[m][6].y, acc[m][7].x, acc[m][7].y);
        }
    }
}

// ---------------- K4: edge layer 1 + fused node2 ----------------
// Warp per dst; 4 lanes per edge (lane = head = float4). 8 edges in flight,
// unroll 2. W2 weights in SHARED memory (frees 16 regs -> higher occupancy).
__global__ void __launch_bounds__(256, 6)
edge1_kernel(const float* __restrict__ a1,
             const float* __restrict__ b1,
             const float* __restrict__ W2l,
             const float* __restrict__ W2r) {
    __shared__ float sW[256];   // [k][16]: c<8 -> W2l col c, c>=8 -> W2r col c-8
    int t = threadIdx.x;
    if (t < 128) {
        int k = t >> 3, c = t & 7;
        sW[k * 16 + c]     = W2l[t];
        sW[k * 16 + 8 + c] = W2r[t];
    }
    __syncthreads();

    int warp = (blockIdx.x * blockDim.x + t) >> 5;   // grid = exactly NN warps
    int lane = t & 31;
    int h = lane & 3;            // head / float4 index
    int eg = lane >> 2;          // edge slot 0..7

    int d = warp;
    int cnt = g_cnt[d];
    int len = cnt < K_SLOT ? cnt : K_SLOT;
    const int* ep = g_esrc2 + d * K_SLOT;

    float4 aa = __ldg((const float4*)a1 + h);
    float4 xr = *((const float4*)(g_xr1 + d * 16) + h);

    float4 acc = make_float4(0.f, 0.f, 0.f, 0.f);
    float den = 0.0f;
    int lenUp = (len + 7) & ~7;
#pragma unroll 2
    for (int j = eg; j < lenUp; j += 8) {
        bool valid = j < len;
        int s = valid ? ep[j] : 0;
        float4 xl = *((const float4*)(g_xl1 + s * 16) + h);
        float lg = aa.x * lrelu02(xl.x + xr.x)
                 + aa.y * lrelu02(xl.y + xr.y)
                 + aa.z * lrelu02(xl.z + xr.z)
                 + aa.w * lrelu02(xl.w + xr.w);
        float ex = valid ? __expf(lg) : 0.0f;
        den += ex;
        acc.x = fmaf(ex, xl.x, acc.x);
        acc.y = fmaf(ex, xl.y, acc.y);
        acc.z = fmaf(ex, xl.z, acc.z);
        acc.w = fmaf(ex, xl.w, acc.w);
    }
    // spill fallback (empty in practice)
    if (cnt > K_SLOT) {
        int ns = g_spill_cnt; if (ns > SPILL_MAX) ns = SPILL_MAX;
        for (int q = 0; q < ns; q++) {
            if (g_spill_d[q] == d && eg == 0) {
                int s = g_spill_s[q];
                float4 xl = *((const float4*)(g_xl1 + s * 16) + h);
                float lg = aa.x * lrelu02(xl.x + xr.x)
                         + aa.y * lrelu02(xl.y + xr.y)
                         + aa.z * lrelu02(xl.z + xr.z)
                         + aa.w * lrelu02(xl.w + xr.w);
                float ex = __expf(lg);
                den += ex;
                acc.x = fmaf(ex, xl.x, acc.x);
                acc.y = fmaf(ex, xl.y, acc.y);
                acc.z = fmaf(ex, xl.z, acc.z);
                acc.w = fmaf(ex, xl.w, acc.w);
            }
        }
    }
    // reduce across 8 edge groups
#pragma unroll
    for (int o = 4; o < 32; o <<= 1) {
        acc.x += __shfl_xor_sync(0xFFFFFFFFu, acc.x, o);
        acc.y += __shfl_xor_sync(0xFFFFFFFFu, acc.y, o);
        acc.z += __shfl_xor_sync(0xFFFFFFFFu, acc.z, o);
        acc.w += __shfl_xor_sync(0xFFFFFFFFu, acc.w, o);
        den   += __shfl_xor_sync(0xFFFFFFFFu, den, o);
    }

    // fused node2: normalize + bias + ELU (every lane has its head's result)
    float inv = 1.0f / (den + 1e-16f);
    float4 bb = __ldg((const float4*)b1 + h);
    float v4[4];
    {
        float t0 = acc.x * inv + bb.x;
        float t1 = acc.y * inv + bb.y;
        float t2 = acc.z * inv + bb.z;
        float t3 = acc.w * inv + bb.w;
        v4[0] = (t0 > 0.0f) ? t0 : (__expf(t0) - 1.0f);
        v4[1] = (t1 > 0.0f) ? t1 : (__expf(t1) - 1.0f);
        v4[2] = (t2 > 0.0f) ? t2 : (__expf(t2) - 1.0f);
        v4[3] = (t3 > 0.0f) ? t3 : (__expf(t3) - 1.0f);
    }
    // 16-wide transform: v[k] lives in lane (k>>2) (replicated mod 4), reg k&3
    int cc = lane & 15;
    float o = 0.0f;
#pragma unroll
    for (int k = 0; k < 16; k++) {
        float vk = __shfl_sync(0xFFFFFFFFu, v4[k & 3], k >> 2);
        o = fmaf(vk, sW[k * 16 + cc], o);
    }
    if (lane < 8)       g_xl2[d * 8 + lane] = o;
    else if (lane < 16) g_xr2[d * 8 + (lane - 8)] = o;
}

// ---------------- K5: edge layer 2 — 2 lanes per edge, fused output --------
__global__ void __launch_bounds__(256, 6)
edge2_kernel(const float* __restrict__ a2,
             const float* __restrict__ b2,
             float* __restrict__ out) {
    int warp = (blockIdx.x * blockDim.x + threadIdx.x) >> 5;
    int lane = threadIdx.x & 31;
    int hf = lane & 1;           // which float4 half of the 8 channels
    int eg = lane >> 1;          // edge slot 0..15

    int d = warp;
    int cnt = g_cnt[d];
    int len = cnt < K_SLOT ? cnt : K_SLOT;
    const int* ep = g_esrc2 + d * K_SLOT;

    float4 aa = __ldg((const float4*)a2 + hf);
    float4 xr = *((const float4*)(g_xr2 + d * 8) + hf);

    float4 acc = make_float4(0.f, 0.f, 0.f, 0.f);
    float den = 0.0f;
    int lenUp = (len + 15) & ~15;
#pragma unroll 2
    for (int j = eg; j < lenUp; j += 16) {
        bool valid = j < len;
        int s = valid ? ep[j] : 0;
        float4 xl = *((const float4*)(g_xl2 + s * 8) + hf);
        float t = aa.x * lrelu02(xl.x + xr.x)
                + aa.y * lrelu02(xl.y + xr.y)
                + aa.z * lrelu02(xl.z + xr.z)
                + aa.w * lrelu02(xl.w + xr.w);
        t += __shfl_xor_sync(0xFFFFFFFFu, t, 1);
        float ex = valid ? __expf(t) : 0.0f;
        den += ex;
        acc.x = fmaf(ex, xl.x, acc.x);
        acc.y = fmaf(ex, xl.y, acc.y);
        acc.z = fmaf(ex, xl.z, acc.z);
        acc.w = fmaf(ex, xl.w, acc.w);
    }
    if (cnt > K_SLOT) {
        int ns = g_spill_cnt; if (ns > SPILL_MAX) ns = SPILL_MAX;
        for (int q = 0; q < ns; q++) {
            if (g_spill_d[q] == d && eg == 0) {
                int s = g_spill_s[q];
                float4 xl = *((const float4*)(g_xl2 + s * 8) + hf);
                float t = aa.x * lrelu02(xl.x + xr.x)
                        + aa.y * lrelu02(xl.y + xr.y)
                        + aa.z * lrelu02(xl.z + xr.z)
                        + aa.w * lrelu02(xl.w + xr.w);
                t += __shfl_xor_sync(0x3u, t, 1);
                float ex = __expf(t);
                den += ex;
                acc.x = fmaf(ex, xl.x, acc.x);
                acc.y = fmaf(ex, xl.y, acc.y);
                acc.z = fmaf(ex, xl.z, acc.z);
                acc.w = fmaf(ex, xl.w, acc.w);
            }
        }
    }
    // reduce across 16 edge groups (keep the lane pair distinct: skip xor 1)
#pragma unroll
    for (int o = 2; o < 32; o <<= 1) {
        acc.x += __shfl_xor_sync(0xFFFFFFFFu, acc.x, o);
        acc.y += __shfl_xor_sync(0xFFFFFFFFu, acc.y, o);
        acc.z += __shfl_xor_sync(0xFFFFFFFFu, acc.z, o);
        acc.w += __shfl_xor_sync(0xFFFFFFFFu, acc.w, o);
        den   += __shfl_xor_sync(0xFFFFFFFFu, den, o);
    }

    if (lane < 2) {   // lane 0: channels 0-3, lane 1: channels 4-7
        float inv = 1.0f / (den + 1e-16f);
        float4 bb = __ldg((const float4*)b2 + lane);
        float4 r;
        r.x = 1.0f / (1.0f + __expf(-(acc.x * inv + bb.x)));
        r.y = 1.0f / (1.0f + __expf(-(acc.y * inv + bb.y)));
        r.z = 1.0f / (1.0f + __expf(-(acc.z * inv + bb.z)));
        r.w = 1.0f / (1.0f + __expf(-(acc.w * inv + bb.w)));
        *((float4*)(out + d * 8) + lane) = r;
    }
}

// ---------------- launch ----------------
extern "C" void kernel_launch(void* const* d_in, const int* in_sizes, int n_in,
                              void* d_out, int out_size) {
    const float* x   = (const float*)d_in[0];
    const void*  ei  = d_in[1];
    const float* W1l = (const float*)d_in[2];
    const float* W1r = (const float*)d_in[3];
    const float* a1  = (const float*)d_in[4];
    const float* b1  = (const float*)d_in[5];
    const float* W2l = (const float*)d_in[6];
    const float* W2r = (const float*)d_in[7];
    const float* a2  = (const float*)d_in[8];
    const float* b2  = (const float*)d_in[9];
    float* out = (float*)d_out;

    static bool configured = false;
    static cudaStream_t s2;
    static cudaEvent_t evA, evB;
    if (!configured) {
        cudaFuncSetAttribute(gemm1_kernel,
                             cudaFuncAttributeMaxDynamicSharedMemorySize,
                             (int)G_SMEM);
        cudaStreamCreateWithFlags(&s2, cudaStreamNonBlocking);
        cudaEventCreateWithFlags(&evA, cudaEventDisableTiming);
        cudaEventCreateWithFlags(&evB, cudaEventDisableTiming);
        configured = true;
    }

    const int EB = (EE + 255) / 256;
    const int NWB = (NN * 32) / 256;   // exactly 12500 blocks, 100000 warps

    // fork: gemm1 on s2 in parallel with CSR build on default stream
    cudaEventRecord(evA, 0);
    cudaStreamWaitEvent(s2, evA, 0);
    gemm1_kernel<<<(NN + G_NODES - 1) / G_NODES, 256, G_SMEM, s2>>>(x, W1l, W1r);
    cudaEventRecord(evB, s2);

    init_kernel<<<(NN + 1023) / 1024, 1024>>>((const long long*)ei);
    build_kernel<<<EB, 256>>>(ei);

    // join
    cudaStreamWaitEvent(0, evB, 0);
    edge1_kernel<<<NWB, 256>>>(a1, b1, W2l, W2r);
    edge2_kernel<<<NWB, 256>>>(a2, b2, out);
}

// round 9
// speedup vs baseline: 1.4915x; 1.0503x over previous
#include <cuda_runtime.h>
#include <cuda_bf16.h>

#define NN 100000
#define EE 3200000
#define K_SLOT 80
#define SPILL_MAX 65536

// ---------------- scratch (device globals; no allocations) ----------------
__device__ int   g_esrc2[NN * K_SLOT];   // bucketed src per dst (fixed stride)
__device__ int   g_cnt[NN];
__device__ int   g_spill_s[SPILL_MAX];
__device__ int   g_spill_d[SPILL_MAX];
__device__ int   g_spill_cnt;
__device__ float g_xl1[NN * 16];
__device__ float g_xr1[NN * 16];
__device__ float g_xl2[NN * 8];
__device__ float g_xr2[NN * 8];
__device__ int   g_is64;

// ---------------- helpers ----------------
__device__ __forceinline__ float lrelu02(float x) {
    return fmaxf(x, 0.2f * x);
}

__device__ __forceinline__ void fma2(float2& d, float2 a, float2 b, float2 c) {
    asm("fma.rn.f32x2 %0, %1, %2, %3;"
        : "=l"(reinterpret_cast<unsigned long long&>(d))
        : "l"(reinterpret_cast<unsigned long long&>(a)),
          "l"(reinterpret_cast<unsigned long long&>(b)),
          "l"(reinterpret_cast<unsigned long long&>(c)));
}

// ---------------- K1: zero counters + detect dtype ----------------
__global__ void init_kernel(const long long* __restrict__ ei) {
    int i = blockIdx.x * blockDim.x + threadIdx.x;
    if (i < NN) g_cnt[i] = 0;
    if (blockIdx.x == 0) {
        if (threadIdx.x == 0) g_spill_cnt = 0;
        int bad = 0;
        for (int j = threadIdx.x; j < 2048; j += 1024) {
            long long v = ei[j];
            if (v < 0 || v >= (long long)NN) bad = 1;
        }
        bad = __syncthreads_or(bad);
        if (threadIdx.x == 0) g_is64 = bad ? 0 : 1;
    }
}

// ---------------- K2: single-pass bucket build (2 edges/thread, 16B loads) --
__global__ void build_kernel(const void* __restrict__ ei) {
    int i = (blockIdx.x * blockDim.x + threadIdx.x) * 2;
    if (i >= EE) return;
    int s0, s1, d0, d1;
    if (g_is64) {
        longlong2 sv = *(const longlong2*)((const long long*)ei + i);
        longlong2 dv = *(const longlong2*)((const long long*)ei + EE + i);
        s0 = (int)sv.x; s1 = (int)sv.y;
        d0 = (int)dv.x; d1 = (int)dv.y;
    } else {
        int2 sv = *(const int2*)((const int*)ei + i);
        int2 dv = *(const int2*)((const int*)ei + EE + i);
        s0 = sv.x; s1 = sv.y;
        d0 = dv.x; d1 = dv.y;
    }
    int p0 = atomicAdd(&g_cnt[d0], 1);
    if (p0 < K_SLOT) {
        g_esrc2[d0 * K_SLOT + p0] = s0;
    } else {
        int q = atomicAdd(&g_spill_cnt, 1);
        if (q < SPILL_MAX) { g_spill_s[q] = s0; g_spill_d[q] = d0; }
    }
    int p1 = atomicAdd(&g_cnt[d1], 1);
    if (p1 < K_SLOT) {
        g_esrc2[d1 * K_SLOT + p1] = s1;
    } else {
        int q = atomicAdd(&g_spill_cnt, 1);
        if (q < SPILL_MAX) { g_spill_s[q] = s1; g_spill_d[q] = d1; }
    }
}

// ---------------- K3: GEMM1 — f32x2 packed FMA ----------------
#define G_NODES 512
#define G_KC    16
#define G_XS    (G_KC + 1)
#define G_SMEM  ((256 * 32 + G_NODES * G_XS) * sizeof(float))

__global__ void __launch_bounds__(256, 2)
gemm1_kernel(const float* __restrict__ x,
             const float* __restrict__ W1l,
             const float* __restrict__ W1r) {
    extern __shared__ float smem[];
    float* Ws = smem;                 // [256 k][32 c]
    float* xs = smem + 256 * 32;      // [512 node][G_XS]

    int t = threadIdx.x;
    for (int i = t; i < 256 * 16; i += 256) {
        int k = i >> 4, c = i & 15;
        Ws[k * 32 + c]      = W1l[i];
        Ws[k * 32 + 16 + c] = W1r[i];
    }

    int nodeBase = blockIdx.x * G_NODES;
    int half = t & 1;
    int ng = (t >> 1) * 4;

    float2 acc[4][8];
#pragma unroll
    for (int m = 0; m < 4; m++)
#pragma unroll
        for (int j = 0; j < 8; j++) acc[m][j] = make_float2(0.f, 0.f);

    for (int kc = 0; kc < 256; kc += G_KC) {
        __syncthreads();
#pragma unroll
        for (int it = 0; it < 8; it++) {
            int idx = t + 256 * it;
            int node = idx >> 2;
            int k4 = (idx & 3) * 4;
            int gnode = nodeBase + node;
            float4 v = (gnode < NN)
                ? *(const float4*)(x + (size_t)gnode * 256 + kc + k4)
                : make_float4(0.f, 0.f, 0.f, 0.f);
            float* p = xs + node * G_XS + k4;
            p[0] = v.x; p[1] = v.y; p[2] = v.z; p[3] = v.w;
        }
        __syncthreads();

#pragma unroll
        for (int k = 0; k < G_KC; k++) {
            const float4* wp = (const float4*)&Ws[(kc + k) * 32 + half * 16];
            float4 w0 = wp[0], w1 = wp[1], w2 = wp[2], w3 = wp[3];
            float2 w[8];
            w[0] = make_float2(w0.x, w0.y); w[1] = make_float2(w0.z, w0.w);
            w[2] = make_float2(w1.x, w1.y); w[3] = make_float2(w1.z, w1.w);
            w[4] = make_float2(w2.x, w2.y); w[5] = make_float2(w2.z, w2.w);
            w[6] = make_float2(w3.x, w3.y); w[7] = make_float2(w3.z, w3.w);
#pragma unroll
            for (int m = 0; m < 4; m++) {
                float xm = xs[(ng + m) * G_XS + k];
                float2 xp = make_float2(xm, xm);
#pragma unroll
                for (int j = 0; j < 8; j++)
                    fma2(acc[m][j], xp, w[j], acc[m][j]);
            }
        }
    }

    float* base = half ? g_xr1 : g_xl1;
#pragma unroll
    for (int m = 0; m < 4; m++) {
        int node = nodeBase + ng + m;
        if (node < NN) {
            float* dstp = base + node * 16;
            *(float4*)(dstp + 0)  = make_float4(acc[m][0].x, acc[m][0].y, acc[m][1].x, acc[m][1].y);
            *(float4*)(dstp + 4)  = make_float4(acc[m][2].x, acc[m][2].y, acc[m][3].x, acc[m][3].y);
            *(float4*)(dstp + 8)  = make_float4(acc[m][4].x, acc[m][4].y, acc[m][5].x, acc[m][5].y);
            *(float4*)(dstp + 12) = make_float4(acc[m][6].x, acc[m][6].y, acc[m][7].x, acc[m][7].y);
        }
    }
}

// ---------------- K4: edge layer 1 + fused node2 ----------------
// 128-thread blocks, 14 CTAs/SM (56 warps = 87.5% theoretical occupancy).
// Warp per dst; 4 lanes per edge (lane = head = float4), 8 edges in flight.
__global__ void __launch_bounds__(128, 14)
edge1_kernel(const float* __restrict__ a1,
             const float* __restrict__ b1,
             const float* __restrict__ W2l,
             const float* __restrict__ W2r) {
    __shared__ float sW[256];   // [k][16]: c<8 -> W2l col c, c>=8 -> W2r col c-8
    int t = threadIdx.x;
    {
        int k = t >> 3, c = t & 7;
        sW[k * 16 + c]     = W2l[t];
        sW[k * 16 + 8 + c] = W2r[t];
    }
    __syncthreads();

    int warp = (blockIdx.x * blockDim.x + t) >> 5;   // grid = exactly NN warps
    int lane = t & 31;
    int h = lane & 3;            // head / float4 index
    int eg = lane >> 2;          // edge slot 0..7

    int d = warp;
    int cnt = g_cnt[d];
    int len = cnt < K_SLOT ? cnt : K_SLOT;
    const int* ep = g_esrc2 + d * K_SLOT;

    float4 aa = __ldg((const float4*)a1 + h);
    float4 xr = *((const float4*)(g_xr1 + d * 16) + h);

    float4 acc = make_float4(0.f, 0.f, 0.f, 0.f);
    float den = 0.0f;
    int lenUp = (len + 7) & ~7;
#pragma unroll 2
    for (int j = eg; j < lenUp; j += 8) {
        bool valid = j < len;
        int s = valid ? ep[j] : 0;
        float4 xl = *((const float4*)(g_xl1 + s * 16) + h);
        float lg = aa.x * lrelu02(xl.x + xr.x)
                 + aa.y * lrelu02(xl.y + xr.y)
                 + aa.z * lrelu02(xl.z + xr.z)
                 + aa.w * lrelu02(xl.w + xr.w);
        float ex = valid ? __expf(lg) : 0.0f;
        den += ex;
        acc.x = fmaf(ex, xl.x, acc.x);
        acc.y = fmaf(ex, xl.y, acc.y);
        acc.z = fmaf(ex, xl.z, acc.z);
        acc.w = fmaf(ex, xl.w, acc.w);
    }
    // spill fallback (empty in practice)
    if (cnt > K_SLOT) {
        int ns = g_spill_cnt; if (ns > SPILL_MAX) ns = SPILL_MAX;
        for (int q = 0; q < ns; q++) {
            if (g_spill_d[q] == d && eg == 0) {
                int s = g_spill_s[q];
                float4 xl = *((const float4*)(g_xl1 + s * 16) + h);
                float lg = aa.x * lrelu02(xl.x + xr.x)
                         + aa.y * lrelu02(xl.y + xr.y)
                         + aa.z * lrelu02(xl.z + xr.z)
                         + aa.w * lrelu02(xl.w + xr.w);
                float ex = __expf(lg);
                den += ex;
                acc.x = fmaf(ex, xl.x, acc.x);
                acc.y = fmaf(ex, xl.y, acc.y);
                acc.z = fmaf(ex, xl.z, acc.z);
                acc.w = fmaf(ex, xl.w, acc.w);
            }
        }
    }
    // reduce across 8 edge groups
#pragma unroll
    for (int o = 4; o < 32; o <<= 1) {
        acc.x += __shfl_xor_sync(0xFFFFFFFFu, acc.x, o);
        acc.y += __shfl_xor_sync(0xFFFFFFFFu, acc.y, o);
        acc.z += __shfl_xor_sync(0xFFFFFFFFu, acc.z, o);
        acc.w += __shfl_xor_sync(0xFFFFFFFFu, acc.w, o);
        den   += __shfl_xor_sync(0xFFFFFFFFu, den, o);
    }

    // fused node2: normalize + bias + ELU (every lane has its head's result)
    float inv = 1.0f / (den + 1e-16f);
    float4 bb = __ldg((const float4*)b1 + h);
    float v4[4];
    {
        float t0 = acc.x * inv + bb.x;
        float t1 = acc.y * inv + bb.y;
        float t2 = acc.z * inv + bb.z;
        float t3 = acc.w * inv + bb.w;
        v4[0] = (t0 > 0.0f) ? t0 : (__expf(t0) - 1.0f);
        v4[1] = (t1 > 0.0f) ? t1 : (__expf(t1) - 1.0f);
        v4[2] = (t2 > 0.0f) ? t2 : (__expf(t2) - 1.0f);
        v4[3] = (t3 > 0.0f) ? t3 : (__expf(t3) - 1.0f);
    }
    // 16-wide transform: v[k] lives in lane (k>>2) (replicated mod 4), reg k&3
    int cc = lane & 15;
    float o = 0.0f;
#pragma unroll
    for (int k = 0; k < 16; k++) {
        float vk = __shfl_sync(0xFFFFFFFFu, v4[k & 3], k >> 2);
        o = fmaf(vk, sW[k * 16 + cc], o);
    }
    if (lane < 8)       g_xl2[d * 8 + lane] = o;
    else if (lane < 16) g_xr2[d * 8 + (lane - 8)] = o;
}

// ---------------- K5: edge layer 2 — 2 lanes per edge, fused output --------
__global__ void __launch_bounds__(128, 14)
edge2_kernel(const float* __restrict__ a2,
             const float* __restrict__ b2,
             float* __restrict__ out) {
    int warp = (blockIdx.x * blockDim.x + threadIdx.x) >> 5;
    int lane = threadIdx.x & 31;
    int hf = lane & 1;           // which float4 half of the 8 channels
    int eg = lane >> 1;          // edge slot 0..15

    int d = warp;
    int cnt = g_cnt[d];
    int len = cnt < K_SLOT ? cnt : K_SLOT;
    const int* ep = g_esrc2 + d * K_SLOT;

    float4 aa = __ldg((const float4*)a2 + hf);
    float4 xr = *((const float4*)(g_xr2 + d * 8) + hf);

    float4 acc = make_float4(0.f, 0.f, 0.f, 0.f);
    float den = 0.0f;
    int lenUp = (len + 15) & ~15;
#pragma unroll 2
    for (int j = eg; j < lenUp; j += 16) {
        bool valid = j < len;
        int s = valid ? ep[j] : 0;
        float4 xl = *((const float4*)(g_xl2 + s * 8) + hf);
        float t = aa.x * lrelu02(xl.x + xr.x)
                + aa.y * lrelu02(xl.y + xr.y)
                + aa.z * lrelu02(xl.z + xr.z)
                + aa.w * lrelu02(xl.w + xr.w);
        t += __shfl_xor_sync(0xFFFFFFFFu, t, 1);
        float ex = valid ? __expf(t) : 0.0f;
        den += ex;
        acc.x = fmaf(ex, xl.x, acc.x);
        acc.y = fmaf(ex, xl.y, acc.y);
        acc.z = fmaf(ex, xl.z, acc.z);
        acc.w = fmaf(ex, xl.w, acc.w);
    }
    if (cnt > K_SLOT) {
        int ns = g_spill_cnt; if (ns > SPILL_MAX) ns = SPILL_MAX;
        for (int q = 0; q < ns; q++) {
            if (g_spill_d[q] == d && eg == 0) {
                int s = g_spill_s[q];
                float4 xl = *((const float4*)(g_xl2 + s * 8) + hf);
                float t = aa.x * lrelu02(xl.x + xr.x)
                        + aa.y * lrelu02(xl.y + xr.y)
                        + aa.z * lrelu02(xl.z + xr.z)
                        + aa.w * lrelu02(xl.w + xr.w);
                t += __shfl_xor_sync(0x3u, t, 1);
                float ex = __expf(t);
                den += ex;
                acc.x = fmaf(ex, xl.x, acc.x);
                acc.y = fmaf(ex, xl.y, acc.y);
                acc.z = fmaf(ex, xl.z, acc.z);
                acc.w = fmaf(ex, xl.w, acc.w);
            }
        }
    }
    // reduce across 16 edge groups (keep the lane pair distinct: skip xor 1)
#pragma unroll
    for (int o = 2; o < 32; o <<= 1) {
        acc.x += __shfl_xor_sync(0xFFFFFFFFu, acc.x, o);
        acc.y += __shfl_xor_sync(0xFFFFFFFFu, acc.y, o);
        acc.z += __shfl_xor_sync(0xFFFFFFFFu, acc.z, o);
        acc.w += __shfl_xor_sync(0xFFFFFFFFu, acc.w, o);
        den   += __shfl_xor_sync(0xFFFFFFFFu, den, o);
    }

    if (lane < 2) {   // lane 0: channels 0-3, lane 1: channels 4-7
        float inv = 1.0f / (den + 1e-16f);
        float4 bb = __ldg((const float4*)b2 + lane);
        float4 r;
        r.x = 1.0f / (1.0f + __expf(-(acc.x * inv + bb.x)));
        r.y = 1.0f / (1.0f + __expf(-(acc.y * inv + bb.y)));
        r.z = 1.0f / (1.0f + __expf(-(acc.z * inv + bb.z)));
        r.w = 1.0f / (1.0f + __expf(-(acc.w * inv + bb.w)));
        *((float4*)(out + d * 8) + lane) = r;
    }
}

// ---------------- launch ----------------
extern "C" void kernel_launch(void* const* d_in, const int* in_sizes, int n_in,
                              void* d_out, int out_size) {
    const float* x   = (const float*)d_in[0];
    const void*  ei  = d_in[1];
    const float* W1l = (const float*)d_in[2];
    const float* W1r = (const float*)d_in[3];
    const float* a1  = (const float*)d_in[4];
    const float* b1  = (const float*)d_in[5];
    const float* W2l = (const float*)d_in[6];
    const float* W2r = (const float*)d_in[7];
    const float* a2  = (const float*)d_in[8];
    const float* b2  = (const float*)d_in[9];
    float* out = (float*)d_out;

    static bool configured = false;
    static cudaStream_t s2;
    static cudaEvent_t evA, evB;
    if (!configured) {
        cudaFuncSetAttribute(gemm1_kernel,
                             cudaFuncAttributeMaxDynamicSharedMemorySize,
                             (int)G_SMEM);
        cudaStreamCreateWithFlags(&s2, cudaStreamNonBlocking);
        cudaEventCreateWithFlags(&evA, cudaEventDisableTiming);
        cudaEventCreateWithFlags(&evB, cudaEventDisableTiming);
        configured = true;
    }

    const int NWB = (NN * 32) / 128;   // 25000 blocks of 128 = 100000 warps

    // fork: gemm1 on s2 in parallel with bucket build on default stream
    cudaEventRecord(evA, 0);
    cudaStreamWaitEvent(s2, evA, 0);
    gemm1_kernel<<<(NN + G_NODES - 1) / G_NODES, 256, G_SMEM, s2>>>(x, W1l, W1r);
    cudaEventRecord(evB, s2);

    init_kernel<<<(NN + 1023) / 1024, 1024>>>((const long long*)ei);
    build_kernel<<<(EE / 2 + 255) / 256, 256>>>(ei);

    // join
    cudaStreamWaitEvent(0, evB, 0);
    edge1_kernel<<<NWB, 128>>>(a1, b1, W2l, W2r);
    edge2_kernel<<<NWB, 128>>>(a2, b2, out);
}